// round 9
// baseline (speedup 1.0000x reference)
#include <cuda_runtime.h>

// DropBlock, single fused launch, occupancy-exact persistent grid.
// x [64,256,64,64] f32, u [58,58] f32. BLOCK_SIZE=7, DROP_PROB=0.1.
//
// Every CTA independently recomputes the 64x64 multiplier table via warp
// ballots (u is 13.5KB, L2-hot; ~16MB total redundant reads across ~1184
// CTAs — negligible), stores it in shared, then grid-strides the 268MB
// elementwise multiply. No cross-CTA dependency; exactly one wave.

#define H 64
#define W 64
#define HW 4096
#define US 58           // H - BS + 1
#define BS 7
#define DROP_PROB 0.1f
#define THREADS 256

typedef unsigned long long u64;

__global__ __launch_bounds__(THREADS)
void dropblock_fused_kernel(const float* __restrict__ u,
                            const float4* __restrict__ x4,
                            float4* __restrict__ out4,
                            int n4) {
    __shared__ u64 s_hdil[US];
    __shared__ u64 s_vdil[H];
    __shared__ int s_sum;
    __shared__ __align__(16) float s_mult[HW];   // 16 KB

    int tid  = threadIdx.x;        // 256 threads = 8 warps
    int lane = tid & 31;
    int warp = tid >> 5;
    if (tid == 0) s_sum = 0;

    // ---- Phase 1: mask via ballots. Warp w -> rows w, w+8, ..., (<58). ----
    // Front-batch all u loads (up to 16 per thread) before any ballot.
    float va[8], vb[8];
    #pragma unroll
    for (int k = 0; k < 8; k++) {
        int row = warp + k * 8;
        if (row < US) {
            const float* r = u + row * US;
            va[k] = __ldg(&r[lane]);
            vb[k] = (lane + 32 < US) ? __ldg(&r[lane + 32]) : 1.0f;
        } else {
            va[k] = 1.0f; vb[k] = 1.0f;
        }
    }
    #pragma unroll
    for (int k = 0; k < 8; k++) {
        int row = warp + k * 8;
        unsigned m0 = __ballot_sync(0xFFFFFFFFu, va[k] < DROP_PROB);
        unsigned m1 = __ballot_sync(0xFFFFFFFFu, vb[k] < DROP_PROB);
        if (row < US && lane == 0) {
            u64 b = (u64)m0 | ((u64)m1 << 32);
            u64 h = b;
            #pragma unroll
            for (int s = 1; s < BS; s++) h |= b << s;   // horizontal dilation
            s_hdil[row] = h;
        }
    }
    __syncthreads();

    // Vertical dilation + keep count (threads 0..63)
    if (tid < H) {
        int i0 = tid - (BS - 1); if (i0 < 0) i0 = 0;
        int i1 = tid;            if (i1 > US - 1) i1 = US - 1;
        u64 v = 0ULL;
        for (int i = i0; i <= i1; i++) v |= s_hdil[i];
        s_vdil[tid] = v;
        int keep = W - __popcll(v);
        #pragma unroll
        for (int off = 16; off > 0; off >>= 1)
            keep += __shfl_down_sync(0xFFFFFFFFu, keep, off);
        if (lane == 0) atomicAdd(&s_sum, keep);
    }
    __syncthreads();

    float scale = (float)HW / (float)s_sum;

    // Fill 16KB table: 1024 float4s over 256 threads = 4 each.
    float4* mt4 = reinterpret_cast<float4*>(s_mult);
    #pragma unroll
    for (int k = 0; k < 4; k++) {
        int q = tid + k * 256;     // float4 index
        int y = q >> 4;            // 16 float4s per row
        int x = (q & 15) * 4;
        u64 v = s_vdil[y];
        float4 f;
        f.x = ((v >> (x + 0)) & 1ULL) ? 0.0f : scale;
        f.y = ((v >> (x + 1)) & 1ULL) ? 0.0f : scale;
        f.z = ((v >> (x + 2)) & 1ULL) ? 0.0f : scale;
        f.w = ((v >> (x + 3)) & 1ULL) ? 0.0f : scale;
        mt4[q] = f;
    }
    __syncthreads();

    // ---- Phase 2: grid-stride streaming multiply ----
    int S = gridDim.x * THREADS;
    for (int i = blockIdx.x * THREADS + tid; i < n4; i += S) {
        float4 v = x4[i];
        float4 m = mt4[i & 1023];
        v.x *= m.x; v.y *= m.y; v.z *= m.z; v.w *= m.w;
        out4[i] = v;
    }
}

extern "C" void kernel_launch(void* const* d_in, const int* in_sizes, int n_in,
                              void* d_out, int out_size) {
    const float* x = (const float*)d_in[0];
    const float* u = (const float*)d_in[1];
    float* out = (float*)d_out;

    // Occupancy-exact single-wave grid (host queries are capture-safe).
    int dev = 0;
    cudaGetDevice(&dev);
    int sms = 148;
    cudaDeviceGetAttribute(&sms, cudaDevAttrMultiProcessorCount, dev);
    int nb = 6;
    cudaOccupancyMaxActiveBlocksPerMultiprocessor(
        &nb, dropblock_fused_kernel, THREADS, 0);
    if (nb < 1) nb = 1;
    int blocks = sms * nb;

    int n4 = out_size / 4;   // 16,777,216 float4s
    dropblock_fused_kernel<<<blocks, THREADS>>>(
        u, (const float4*)x, (float4*)out, n4);
}